// round 8
// baseline (speedup 1.0000x reference)
#include <cuda_runtime.h>
#include <cstdint>
#include <math.h>

#define B_   16
#define N_   2048
#define FIN  256
#define H_   128
#define TJ   32

// Scratch (allocation-free: __device__ globals)
__device__ __align__(16) signed char g_wHi[B_ * H_ * N_];  // [b][h][n] s8, w*4096 hi byte
__device__ __align__(16) signed char g_wLo[B_ * H_ * N_];  // [b][h][n] s8, lo byte (signed split)
__device__ float g_src[B_ * N_];
__device__ float g_dst[B_ * N_];
__device__ float g_dstmax[B_];

__device__ __forceinline__ uint32_t smem_u32(const void* p) {
    uint32_t a;
    asm("{ .reg .u64 t; cvta.to.shared.u64 t, %1; cvt.u32.u64 %0, t; }" : "=r"(a) : "l"(p));
    return a;
}

#define LDSM4(r0, r1, r2, r3, addr) \
    asm volatile("ldmatrix.sync.aligned.m8n8.x4.shared.b16 {%0,%1,%2,%3}, [%4];" \
                 : "=r"(r0), "=r"(r1), "=r"(r2), "=r"(r3) : "r"(addr))

#define IMMA_US(d, a0, a1, a2, a3, b0, b1) \
    asm volatile("mma.sync.aligned.m16n8k32.row.col.s32.u8.s8.s32 " \
                 "{%0,%1,%2,%3}, {%4,%5,%6,%7}, {%8,%9}, {%0,%1,%2,%3};" \
                 : "+r"((d)[0]), "+r"((d)[1]), "+r"((d)[2]), "+r"((d)[3]) \
                 : "r"(a0), "r"(a1), "r"(a2), "r"(a3), "r"(b0), "r"(b1))

#define IMMA_SS(d, a0, a1, a2, a3, b0, b1) \
    asm volatile("mma.sync.aligned.m16n8k32.row.col.s32.s8.s8.s32 " \
                 "{%0,%1,%2,%3}, {%4,%5,%6,%7}, {%8,%9}, {%0,%1,%2,%3};" \
                 : "+r"((d)[0]), "+r"((d)[1]), "+r"((d)[2]), "+r"((d)[3]) \
                 : "r"(a0), "r"(a1), "r"(a2), "r"(a3), "r"(b0), "r"(b1))

#define CP_ASYNC16(dst, src) \
    asm volatile("cp.async.cg.shared.global [%0], [%1], 16;" :: "r"(dst), "l"(src))
#define CP_COMMIT()  asm volatile("cp.async.commit_group;" ::: "memory")
#define CP_WAIT0()   asm volatile("cp.async.wait_group 0;" ::: "memory")

// ---------------------------------------------------------------------------
// Kernel A (fused): wh in registers -> int8 planes (transposed) + src/dst.
// ---------------------------------------------------------------------------
__global__ __launch_bounds__(256) void k_proj(const float* __restrict__ inp,
                                              const float* __restrict__ W,
                                              const float* __restrict__ bW,
                                              const float* __restrict__ av,
                                              const float* __restrict__ b_a) {
    __shared__ __align__(16) float A_s[32 * 132];
    __shared__ __align__(16) float W_s[32 * 132];
    int t = threadIdx.x;
    int row0 = blockIdx.x * 128;
    int tr = t >> 4, tc = t & 15;

    float acc[8][8];
#pragma unroll
    for (int i = 0; i < 8; i++)
#pragma unroll
        for (int j = 0; j < 8; j++) acc[i][j] = 0.f;

    for (int k0 = 0; k0 < FIN; k0 += 32) {
#pragma unroll
        for (int v = 0; v < 4; v++) {
            int f4 = t + 256 * v;
            int r = f4 >> 3;
            int c = (f4 & 7) * 4;
            float4 a4 = *(const float4*)(inp + (size_t)(row0 + r) * FIN + k0 + c);
            A_s[(c + 0) * 132 + r] = a4.x;
            A_s[(c + 1) * 132 + r] = a4.y;
            A_s[(c + 2) * 132 + r] = a4.z;
            A_s[(c + 3) * 132 + r] = a4.w;
            float4 b4 = *(const float4*)(W + (size_t)r * FIN + k0 + c);
            W_s[(c + 0) * 132 + r] = b4.x;
            W_s[(c + 1) * 132 + r] = b4.y;
            W_s[(c + 2) * 132 + r] = b4.z;
            W_s[(c + 3) * 132 + r] = b4.w;
        }
        __syncthreads();
#pragma unroll
        for (int kk = 0; kk < 32; kk++) {
            float a[8], b[8];
            *(float4*)&a[0] = *(const float4*)&A_s[kk * 132 + tr * 8];
            *(float4*)&a[4] = *(const float4*)&A_s[kk * 132 + tr * 8 + 4];
            *(float4*)&b[0] = *(const float4*)&W_s[kk * 132 + tc * 8];
            *(float4*)&b[4] = *(const float4*)&W_s[kk * 132 + tc * 8 + 4];
#pragma unroll
            for (int i = 0; i < 8; i++)
#pragma unroll
                for (int j = 0; j < 8; j++)
                    acc[i][j] = fmaf(a[i], b[j], acc[i][j]);
        }
        __syncthreads();
    }

    // ---- epilogue ----
    int h0 = tc * 8;
    int bb = row0 / N_;
    int n0 = (row0 % N_) + tr * 8;

    float bwv[8];
    *(float4*)&bwv[0] = *(const float4*)(bW + h0);
    *(float4*)&bwv[4] = *(const float4*)(bW + h0 + 4);
#pragma unroll
    for (int i = 0; i < 8; i++)
#pragma unroll
        for (int j = 0; j < 8; j++) acc[i][j] += bwv[j];

    // int8 split transposed stores: w_fx = rint(w*4096), hi=(w_fx+128)>>8, lo=w_fx-hi*256
#pragma unroll
    for (int j = 0; j < 8; j++) {
        unsigned hiP[2] = {0u, 0u}, loP[2] = {0u, 0u};
#pragma unroll
        for (int i = 0; i < 8; i++) {
            int wfx = __float2int_rn(acc[i][j] * 4096.f);
            int h8 = (wfx + 128) >> 8;
            int l8 = wfx - (h8 << 8);
            hiP[i >> 2] |= (unsigned)(h8 & 255) << ((i & 3) * 8);
            loP[i >> 2] |= (unsigned)(l8 & 255) << ((i & 3) * 8);
        }
        size_t idx = ((size_t)(bb * H_ + h0 + j)) * N_ + n0;
        *(uint2*)(g_wHi + idx) = make_uint2(hiP[0], hiP[1]);
        *(uint2*)(g_wLo + idx) = make_uint2(loP[0], loP[1]);
    }

    // src/dst reductions
    float a1v[8], a2v[8];
    *(float4*)&a1v[0] = *(const float4*)(av + h0);
    *(float4*)&a1v[4] = *(const float4*)(av + h0 + 4);
    *(float4*)&a2v[0] = *(const float4*)(av + H_ + h0);
    *(float4*)&a2v[4] = *(const float4*)(av + H_ + h0 + 4);

    float s1[8], s2[8];
#pragma unroll
    for (int i = 0; i < 8; i++) {
        float x1 = 0.f, x2 = 0.f;
#pragma unroll
        for (int j = 0; j < 8; j++) {
            x1 = fmaf(acc[i][j], a1v[j], x1);
            x2 = fmaf(acc[i][j], a2v[j], x2);
        }
        s1[i] = x1; s2[i] = x2;
    }
#pragma unroll
    for (int o = 1; o < 16; o <<= 1) {
#pragma unroll
        for (int i = 0; i < 8; i++) {
            s1[i] += __shfl_xor_sync(~0u, s1[i], o);
            s2[i] += __shfl_xor_sync(~0u, s2[i], o);
        }
    }
    if (tc == 0) {
        float ba = b_a[0];
        int r = row0 + tr * 8;
#pragma unroll
        for (int i = 0; i < 8; i++) {
            g_src[r + i] = s1[i] + ba;
            g_dst[r + i] = s2[i];
        }
    }
}

// ---------------------------------------------------------------------------
// Kernel B2: per-batch max of dst.
// ---------------------------------------------------------------------------
__global__ __launch_bounds__(256) void k_dstmax() {
    __shared__ float red[8];
    int b = blockIdx.x, t = threadIdx.x;
    float mx = -1e30f;
#pragma unroll
    for (int v = 0; v < 8; v++) mx = fmaxf(mx, g_dst[b * N_ + t + 256 * v]);
#pragma unroll
    for (int o = 16; o; o >>= 1) mx = fmaxf(mx, __shfl_xor_sync(~0u, mx, o));
    if ((t & 31) == 0) red[t >> 5] = mx;
    __syncthreads();
    if (t == 0) {
        float m2 = red[0];
#pragma unroll
        for (int i = 1; i < 8; i++) m2 = fmaxf(m2, red[i]);
        g_dstmax[b] = m2;
    }
}

// ---------------------------------------------------------------------------
// Kernel C: fused attention via int8 mma.sync m16n8k32 (fixed-point split).
//
// p16 = rint(p*65280): hi u8 + lo s8.  w16 = rint(w*4096): hi s8 + lo s8.
// p*w = (65536*h8*wh + 256*(h8*wl + l8*wh) + l8*wl) / (65280*4096)
// 3 MMAs per n8: hh (u8xs8) -> Chh; hi*lo (u8xs8) + lo*hi (s8xs8) -> Cmid.
// out = Chh/4080 + Cmid/1044480.  lo*lo dropped (zero-mean, ~1e-4 rel).
// ---------------------------------------------------------------------------
#define SBUF 18432u
#define OPL  6144u
#define OWH  12288u
#define OWL  15360u
#define OLS  36864u
#define DYNB 37376

__global__ __launch_bounds__(256, 2) void k_attn_i8(const int* __restrict__ adj,
                                                    float* __restrict__ out) {
    extern __shared__ __align__(16) char dyn[];
    uint32_t sb = smem_u32(dyn);

    int t = threadIdx.x;
    int w = t >> 5, lane = t & 31;
    int ti = t >> 1, q = t & 1;
    int b = blockIdx.y;
    int ibase = (blockIdx.x >> 1) * 128;
    int hbase = (blockIdx.x & 1) * 64;

    float my_src = g_src[b * N_ + ibase + ti];
    float mb = my_src + g_dstmax[b];
    float m = mb > 0.f ? mb : 0.01f * mb;
    float l = 0.f;

    const int*   adj_row = adj + ((size_t)(b * N_ + ibase + ti)) * (size_t)N_;
    const float* dst_row = g_dst + b * N_;
    const signed char* wHi_b = g_wHi + ((size_t)(b * H_ + hbase)) * N_;
    const signed char* wLo_b = g_wLo + ((size_t)(b * H_ + hbase)) * N_;

    int Chh[8][4], Cmid[8][4];
#pragma unroll
    for (int nt = 0; nt < 8; nt++)
#pragma unroll
        for (int c = 0; c < 4; c++) { Chh[nt][c] = 0; Cmid[nt][c] = 0; }

    // ldmatrix base addresses (buffer 0)
    uint32_t a_base = sb + (16 * w + (lane & 15)) * 48 + (lane >> 4) * 16;   // Ph
    int bn = ((lane >> 4) & 1) * 8 + (lane & 7);
    uint32_t b_base = sb + OWH + bn * 48 + ((lane >> 3) & 1) * 16;           // Wh

    // W staging: plane = t>>7, row r = (t>>1)&63, half = t&1 (16B each)
    int plane = t >> 7, wr = (t >> 1) & 63, wh2 = t & 1;
    uint32_t wdst = sb + OWH + plane * 3072 + wr * 48 + wh2 * 16;
    const signed char* wsrc = (plane ? wLo_b : wHi_b) + (size_t)wr * N_ + wh2 * 16;

    // ---- prologue: stage W(0), prefetch adj(0) ----
    CP_ASYNC16(wdst, wsrc);
    CP_COMMIT();

    int4 adjp[4];
    {
        const int4* a4 = (const int4*)(adj_row + q * 16);
#pragma unroll
        for (int v = 0; v < 4; v++) adjp[v] = a4[v];
    }

    for (int tile = 0; tile < 64; tile++) {
        int s = tile & 1;
        int j0 = tile * TJ;

        // ---- score phase: p -> 16-bit fixed, hi/lo packed bytes ----
        {
            const float4* d4 = (const float4*)(dst_row + j0 + q * 16);
            unsigned hiP[4], loP[4];
#pragma unroll
            for (int v2 = 0; v2 < 4; v2++) {
                int4 av = adjp[v2];
                float4 dv = d4[v2];
                unsigned hu = 0, lu = 0;
                float sc, p;
                int pi, h8, l8;
                sc = my_src + dv.x; sc = sc > 0.f ? sc : 0.01f * sc;
                p = av.x > 0 ? __expf(sc - m) : 0.f; l += p;
                pi = __float2int_rn(p * 65280.f);
                h8 = (pi + 128) >> 8; l8 = pi - (h8 << 8);
                hu |= (unsigned)h8; lu |= (unsigned)(l8 & 255);
                sc = my_src + dv.y; sc = sc > 0.f ? sc : 0.01f * sc;
                p = av.y > 0 ? __expf(sc - m) : 0.f; l += p;
                pi = __float2int_rn(p * 65280.f);
                h8 = (pi + 128) >> 8; l8 = pi - (h8 << 8);
                hu |= (unsigned)h8 << 8; lu |= (unsigned)(l8 & 255) << 8;
                sc = my_src + dv.z; sc = sc > 0.f ? sc : 0.01f * sc;
                p = av.z > 0 ? __expf(sc - m) : 0.f; l += p;
                pi = __float2int_rn(p * 65280.f);
                h8 = (pi + 128) >> 8; l8 = pi - (h8 << 8);
                hu |= (unsigned)h8 << 16; lu |= (unsigned)(l8 & 255) << 16;
                sc = my_src + dv.w; sc = sc > 0.f ? sc : 0.01f * sc;
                p = av.w > 0 ? __expf(sc - m) : 0.f; l += p;
                pi = __float2int_rn(p * 65280.f);
                h8 = (pi + 128) >> 8; l8 = pi - (h8 << 8);
                hu |= (unsigned)h8 << 24; lu |= (unsigned)(l8 & 255) << 24;
                hiP[v2] = hu; loP[v2] = lu;
            }
            uint32_t poff = s * SBUF + ti * 48 + q * 16;
            *(uint4*)(dyn + poff)        = make_uint4(hiP[0], hiP[1], hiP[2], hiP[3]);
            *(uint4*)(dyn + poff + OPL)  = make_uint4(loP[0], loP[1], loP[2], loP[3]);
        }

        // ---- prefetch adj(tile+1) ----
        {
            int jn = ((tile + 1) & 63) * TJ;
            const int4* a4 = (const int4*)(adj_row + jn + q * 16);
#pragma unroll
            for (int v = 0; v < 4; v++) adjp[v] = a4[v];
        }

        CP_WAIT0();        // W(tile) landed
        __syncthreads();   // P(s) visible; MMA(tile-1) done with buffer s^1

        // ---- stage W(tile+1) into buffer s^1 (overlaps MMA) ----
        if (tile < 63) {
            int jn = (tile + 1) * TJ;
            CP_ASYNC16(wdst + (s ^ 1) * SBUF, wsrc + jn);
            CP_COMMIT();
        }

        // ---- MMA phase on buffer s ----
        uint32_t aoff = s * SBUF;
        uint32_t Ah0, Ah1, Ah2, Ah3, Al0, Al1, Al2, Al3;
        LDSM4(Ah0, Ah1, Ah2, Ah3, a_base + aoff);
        LDSM4(Al0, Al1, Al2, Al3, a_base + aoff + OPL);
#pragma unroll
        for (int g = 0; g < 4; g++) {
            uint32_t Bh0, Bh1, Bh2, Bh3, Bl0, Bl1, Bl2, Bl3;
            LDSM4(Bh0, Bh1, Bh2, Bh3, b_base + aoff + g * 768);
            LDSM4(Bl0, Bl1, Bl2, Bl3, b_base + aoff + g * 768 + 3072);
            IMMA_US(Chh[2 * g + 0], Ah0, Ah1, Ah2, Ah3, Bh0, Bh1);
            IMMA_US(Cmid[2 * g + 0], Ah0, Ah1, Ah2, Ah3, Bl0, Bl1);
            IMMA_SS(Cmid[2 * g + 0], Al0, Al1, Al2, Al3, Bh0, Bh1);
            IMMA_US(Chh[2 * g + 1], Ah0, Ah1, Ah2, Ah3, Bh2, Bh3);
            IMMA_US(Cmid[2 * g + 1], Ah0, Ah1, Ah2, Ah3, Bl2, Bl3);
            IMMA_SS(Cmid[2 * g + 1], Al0, Al1, Al2, Al3, Bh2, Bh3);
        }
    }

    l += __shfl_xor_sync(~0u, l, 1);
    float* l_s = (float*)(dyn + OLS);
    if (q == 0) l_s[ti] = l;
    __syncthreads();

    // ---- epilogue: combine fixed-point, normalize, ELU, store ----
    {
        int r0 = 16 * w + (lane >> 2);
        int r1 = r0 + 8;
        float inv0 = 1.0f / l_s[r0];
        float inv1 = 1.0f / l_s[r1];
        float* orow0 = out + ((size_t)(b * N_ + ibase + r0)) * H_ + hbase;
        float* orow1 = out + ((size_t)(b * N_ + ibase + r1)) * H_ + hbase;
        int hoff = (lane & 3) * 2;
        const float SH = 1.0f / 4080.0f;      // 65536/(65280*4096)
        const float SM = 1.0f / 1044480.0f;   // 256/(65280*4096)
#pragma unroll
        for (int nt = 0; nt < 8; nt++) {
            int h = nt * 8 + hoff;
            float x;
            float2 o;
            x = fmaf((float)Chh[nt][0], SH, (float)Cmid[nt][0] * SM) * inv0;
            o.x = x > 0.f ? x : expm1f(x);
            x = fmaf((float)Chh[nt][1], SH, (float)Cmid[nt][1] * SM) * inv0;
            o.y = x > 0.f ? x : expm1f(x);
            *(float2*)(orow0 + h) = o;
            x = fmaf((float)Chh[nt][2], SH, (float)Cmid[nt][2] * SM) * inv1;
            o.x = x > 0.f ? x : expm1f(x);
            x = fmaf((float)Chh[nt][3], SH, (float)Cmid[nt][3] * SM) * inv1;
            o.y = x > 0.f ? x : expm1f(x);
            *(float2*)(orow1 + h) = o;
        }
    }
}

// ---------------------------------------------------------------------------
extern "C" void kernel_launch(void* const* d_in, const int* in_sizes, int n_in,
                              void* d_out, int out_size) {
    const float* inputs = (const float*)d_in[0];
    const int*   adj    = (const int*)d_in[1];
    const float* W      = (const float*)d_in[2];
    const float* bW     = (const float*)d_in[3];
    const float* a      = (const float*)d_in[4];
    const float* b_a    = (const float*)d_in[5];
    float* out = (float*)d_out;

    cudaFuncSetAttribute(k_attn_i8, cudaFuncAttributeMaxDynamicSharedMemorySize, DYNB);

    k_proj<<<(B_ * N_) / 128, 256>>>(inputs, W, bW, a, b_a);
    k_dstmax<<<B_, 256>>>();
    k_attn_i8<<<dim3(32, B_), 256, DYNB>>>(adj, out);
}

// round 9
// speedup vs baseline: 2.1694x; 2.1694x over previous
#include <cuda_runtime.h>
#include <cuda_fp16.h>
#include <cstdint>
#include <math.h>

#define B_   16
#define N_   2048
#define FIN  256
#define H_   128
#define TJ   32

// Scratch (allocation-free: __device__ globals)
__device__ half  g_whT_hi[B_ * H_ * N_];     // [b][h][n] fp16 hi
__device__ half  g_whT_lo[B_ * H_ * N_];     // [b][h][n] fp16 lo (residual)
__device__ float g_src[B_ * N_];             // src + b_a folded in
__device__ float g_dst[B_ * N_];
__device__ float g_dstmax[B_];

__device__ __forceinline__ uint32_t smem_u32(const void* p) {
    uint32_t a;
    asm("{ .reg .u64 t; cvta.to.shared.u64 t, %1; cvt.u32.u64 %0, t; }" : "=r"(a) : "l"(p));
    return a;
}

#define LDSM4(r0, r1, r2, r3, addr) \
    asm volatile("ldmatrix.sync.aligned.m8n8.x4.shared.b16 {%0,%1,%2,%3}, [%4];" \
                 : "=r"(r0), "=r"(r1), "=r"(r2), "=r"(r3) : "r"(addr))

#define MMA16816(d, a0, a1, a2, a3, b0, b1) \
    asm volatile("mma.sync.aligned.m16n8k16.row.col.f32.f16.f16.f32 " \
                 "{%0,%1,%2,%3}, {%4,%5,%6,%7}, {%8,%9}, {%0,%1,%2,%3};" \
                 : "+f"((d)[0]), "+f"((d)[1]), "+f"((d)[2]), "+f"((d)[3]) \
                 : "r"(a0), "r"(a1), "r"(a2), "r"(a3), "r"(b0), "r"(b1))

#define CP_ASYNC16(dst, src) \
    asm volatile("cp.async.cg.shared.global [%0], [%1], 16;" :: "r"(dst), "l"(src))
#define CP_COMMIT()  asm volatile("cp.async.commit_group;" ::: "memory")
#define CP_WAIT0()   asm volatile("cp.async.wait_group 0;" ::: "memory")

// ---------------------------------------------------------------------------
// Kernel A (fused): wh in registers -> whT hi/lo fp16 planes + src/dst.
// ---------------------------------------------------------------------------
__global__ __launch_bounds__(256) void k_proj(const float* __restrict__ inp,
                                              const float* __restrict__ W,
                                              const float* __restrict__ bW,
                                              const float* __restrict__ av,
                                              const float* __restrict__ b_a) {
    __shared__ __align__(16) float A_s[32 * 132];
    __shared__ __align__(16) float W_s[32 * 132];
    int t = threadIdx.x;
    int row0 = blockIdx.x * 128;
    int tr = t >> 4, tc = t & 15;

    float acc[8][8];
#pragma unroll
    for (int i = 0; i < 8; i++)
#pragma unroll
        for (int j = 0; j < 8; j++) acc[i][j] = 0.f;

    for (int k0 = 0; k0 < FIN; k0 += 32) {
#pragma unroll
        for (int v = 0; v < 4; v++) {
            int f4 = t + 256 * v;
            int r = f4 >> 3;
            int c = (f4 & 7) * 4;
            float4 a4 = *(const float4*)(inp + (size_t)(row0 + r) * FIN + k0 + c);
            A_s[(c + 0) * 132 + r] = a4.x;
            A_s[(c + 1) * 132 + r] = a4.y;
            A_s[(c + 2) * 132 + r] = a4.z;
            A_s[(c + 3) * 132 + r] = a4.w;
            float4 b4 = *(const float4*)(W + (size_t)r * FIN + k0 + c);
            W_s[(c + 0) * 132 + r] = b4.x;
            W_s[(c + 1) * 132 + r] = b4.y;
            W_s[(c + 2) * 132 + r] = b4.z;
            W_s[(c + 3) * 132 + r] = b4.w;
        }
        __syncthreads();
#pragma unroll
        for (int kk = 0; kk < 32; kk++) {
            float a[8], b[8];
            *(float4*)&a[0] = *(const float4*)&A_s[kk * 132 + tr * 8];
            *(float4*)&a[4] = *(const float4*)&A_s[kk * 132 + tr * 8 + 4];
            *(float4*)&b[0] = *(const float4*)&W_s[kk * 132 + tc * 8];
            *(float4*)&b[4] = *(const float4*)&W_s[kk * 132 + tc * 8 + 4];
#pragma unroll
            for (int i = 0; i < 8; i++)
#pragma unroll
                for (int j = 0; j < 8; j++)
                    acc[i][j] = fmaf(a[i], b[j], acc[i][j]);
        }
        __syncthreads();
    }

    // ---- epilogue ----
    int h0 = tc * 8;
    int bb = row0 / N_;
    int n0 = (row0 % N_) + tr * 8;

    float bwv[8];
    *(float4*)&bwv[0] = *(const float4*)(bW + h0);
    *(float4*)&bwv[4] = *(const float4*)(bW + h0 + 4);
#pragma unroll
    for (int i = 0; i < 8; i++)
#pragma unroll
        for (int j = 0; j < 8; j++) acc[i][j] += bwv[j];

    // whT hi/lo transposed stores
#pragma unroll
    for (int j = 0; j < 8; j++) {
        __align__(16) half hi8[8];
        __align__(16) half lo8[8];
#pragma unroll
        for (int i = 0; i < 8; i++) {
            half hh = __float2half_rn(acc[i][j]);
            hi8[i] = hh;
            lo8[i] = __float2half_rn(acc[i][j] - __half2float(hh));
        }
        size_t idx = ((size_t)(bb * H_ + h0 + j)) * N_ + n0;
        *(uint4*)(g_whT_hi + idx) = *(uint4*)hi8;
        *(uint4*)(g_whT_lo + idx) = *(uint4*)lo8;
    }

    // src/dst reductions
    float a1v[8], a2v[8];
    *(float4*)&a1v[0] = *(const float4*)(av + h0);
    *(float4*)&a1v[4] = *(const float4*)(av + h0 + 4);
    *(float4*)&a2v[0] = *(const float4*)(av + H_ + h0);
    *(float4*)&a2v[4] = *(const float4*)(av + H_ + h0 + 4);

    float s1[8], s2[8];
#pragma unroll
    for (int i = 0; i < 8; i++) {
        float x1 = 0.f, x2 = 0.f;
#pragma unroll
        for (int j = 0; j < 8; j++) {
            x1 = fmaf(acc[i][j], a1v[j], x1);
            x2 = fmaf(acc[i][j], a2v[j], x2);
        }
        s1[i] = x1; s2[i] = x2;
    }
#pragma unroll
    for (int o = 1; o < 16; o <<= 1) {
#pragma unroll
        for (int i = 0; i < 8; i++) {
            s1[i] += __shfl_xor_sync(~0u, s1[i], o);
            s2[i] += __shfl_xor_sync(~0u, s2[i], o);
        }
    }
    if (tc == 0) {
        float ba = b_a[0];
        int r = row0 + tr * 8;
#pragma unroll
        for (int i = 0; i < 8; i++) {
            g_src[r + i] = s1[i] + ba;
            g_dst[r + i] = s2[i];
        }
    }
}

// ---------------------------------------------------------------------------
// Kernel B2: per-batch max of dst.
// ---------------------------------------------------------------------------
__global__ __launch_bounds__(256) void k_dstmax() {
    __shared__ float red[8];
    int b = blockIdx.x, t = threadIdx.x;
    float mx = -1e30f;
#pragma unroll
    for (int v = 0; v < 8; v++) mx = fmaxf(mx, g_dst[b * N_ + t + 256 * v]);
#pragma unroll
    for (int o = 16; o; o >>= 1) mx = fmaxf(mx, __shfl_xor_sync(~0u, mx, o));
    if ((t & 31) == 0) red[t >> 5] = mx;
    __syncthreads();
    if (t == 0) {
        float m2 = red[0];
#pragma unroll
        for (int i = 1; i < 8; i++) m2 = fmaxf(m2, red[i]);
        g_dstmax[b] = m2;
    }
}

// ---------------------------------------------------------------------------
// Kernel C: fused attention via mma.sync fp16. P stored plain fp16 (no lo
// plane); W split hi/lo. Since ph*wh + ph*wl = ph*w exactly, both MMAs share
// one accumulator: 2 MMAs per n8 (was 3), no Pl smem traffic.
//
// Dynamic smem (bytes from base):  PB = 10240 per-plane-per-buffer
//   Ph[2]: 0, 10240   Wh[2]: 20480, 30720   Wl[2]: 40960, 51200
//   l_s: 61440        total 61952
// ---------------------------------------------------------------------------
#define PB   10240u
#define OWH  20480u
#define OWL  40960u
#define OLS  61440u
#define DYNB 61952

__global__ __launch_bounds__(256, 2) void k_attn_mma(const int* __restrict__ adj,
                                                     float* __restrict__ out) {
    extern __shared__ __align__(16) char dyn[];
    uint32_t sb = smem_u32(dyn);

    int t = threadIdx.x;
    int w = t >> 5, lane = t & 31;
    int ti = t >> 1, q = t & 1;
    int b = blockIdx.y;
    int ibase = blockIdx.x * 128;

    float my_src = g_src[b * N_ + ibase + ti];
    float mb = my_src + g_dstmax[b];
    float m = mb > 0.f ? mb : 0.01f * mb;
    float l = 0.f;

    const int*   adj_row = adj + ((size_t)(b * N_ + ibase + ti)) * (size_t)N_;
    const float* dst_row = g_dst + b * N_;
    const half*  whTh_b  = g_whT_hi + (size_t)b * H_ * N_;
    const half*  whTl_b  = g_whT_lo + (size_t)b * H_ * N_;

    float C[16][4];
#pragma unroll
    for (int nt = 0; nt < 16; nt++)
#pragma unroll
        for (int c = 0; c < 4; c++) C[nt][c] = 0.f;

    // ldmatrix base addresses (buffer 0)
    uint32_t a_base = sb + (16 * w + (lane & 15)) * 80 + (lane >> 4) * 16;   // Ph
    int bn = ((lane >> 4) & 1) * 8 + (lane & 7);
    int bk = ((lane >> 3) & 1) * 8;
    uint32_t b_base = sb + OWH + bn * 80 + bk * 2;                            // Wh

    // W staging: hr = t>>1 row, hf = t&1 half (32B each)
    int hr = t >> 1, hf = t & 1;
    uint32_t wdst_h = sb + OWH + hr * 80 + hf * 32;
    uint32_t wdst_l = sb + OWL + hr * 80 + hf * 32;
    const half* wsrc_h = whTh_b + (size_t)hr * N_ + hf * 16;
    const half* wsrc_l = whTl_b + (size_t)hr * N_ + hf * 16;

    // ---- prologue: stage W(0), prefetch adj(0) ----
    CP_ASYNC16(wdst_h,      wsrc_h);
    CP_ASYNC16(wdst_h + 16, wsrc_h + 8);
    CP_ASYNC16(wdst_l,      wsrc_l);
    CP_ASYNC16(wdst_l + 16, wsrc_l + 8);
    CP_COMMIT();

    int4 adjp[4];
    {
        const int4* a4 = (const int4*)(adj_row + q * 16);
#pragma unroll
        for (int v = 0; v < 4; v++) adjp[v] = a4[v];
    }

    for (int tile = 0; tile < 64; tile++) {
        int s = tile & 1;
        int j0 = tile * TJ;

        // ---- score phase: P(tile) plain fp16 into Ph[s] ----
        {
            const float4* d4 = (const float4*)(dst_row + j0 + q * 16);
            __align__(16) half hs[16];
#pragma unroll
            for (int v2 = 0; v2 < 4; v2++) {
                int4 av = adjp[v2];
                float4 dv = d4[v2];
                float sc, p;
                int jj = v2 * 4;
                sc = my_src + dv.x; sc = sc > 0.f ? sc : 0.01f * sc;
                p = av.x > 0 ? __expf(sc - m) : 0.f; l += p;
                hs[jj + 0] = __float2half_rn(p);
                sc = my_src + dv.y; sc = sc > 0.f ? sc : 0.01f * sc;
                p = av.y > 0 ? __expf(sc - m) : 0.f; l += p;
                hs[jj + 1] = __float2half_rn(p);
                sc = my_src + dv.z; sc = sc > 0.f ? sc : 0.01f * sc;
                p = av.z > 0 ? __expf(sc - m) : 0.f; l += p;
                hs[jj + 2] = __float2half_rn(p);
                sc = my_src + dv.w; sc = sc > 0.f ? sc : 0.01f * sc;
                p = av.w > 0 ? __expf(sc - m) : 0.f; l += p;
                hs[jj + 3] = __float2half_rn(p);
            }
            uint32_t poff = s * PB + ti * 80 + q * 32;
            *(uint4*)(dyn + poff)      = ((uint4*)hs)[0];
            *(uint4*)(dyn + poff + 16) = ((uint4*)hs)[1];
        }

        // ---- prefetch adj(tile+1) ----
        {
            int jn = ((tile + 1) & 63) * TJ;
            const int4* a4 = (const int4*)(adj_row + jn + q * 16);
#pragma unroll
            for (int v = 0; v < 4; v++) adjp[v] = a4[v];
        }

        CP_WAIT0();        // W(tile) landed
        __syncthreads();   // P(s) visible; MMA(tile-1) done with buffer s^1

        // ---- stage W(tile+1) into buffer s^1 (overlaps MMA) ----
        if (tile < 63) {
            int jn = (tile + 1) * TJ;
            uint32_t off = (s ^ 1) * PB;
            CP_ASYNC16(wdst_h + off,      wsrc_h + jn);
            CP_ASYNC16(wdst_h + off + 16, wsrc_h + jn + 8);
            CP_ASYNC16(wdst_l + off,      wsrc_l + jn);
            CP_ASYNC16(wdst_l + off + 16, wsrc_l + jn + 8);
            CP_COMMIT();
        }

        // ---- MMA phase on buffer s: 2 MMAs per n8, shared accumulator ----
        uint32_t aoff = s * PB;
#pragma unroll
        for (int kc = 0; kc < 2; kc++) {
            uint32_t Ah0, Ah1, Ah2, Ah3;
            LDSM4(Ah0, Ah1, Ah2, Ah3, a_base + aoff + kc * 32);
#pragma unroll
            for (int np = 0; np < 8; np++) {
                uint32_t Bh0, Bh1, Bh2, Bh3, Bl0, Bl1, Bl2, Bl3;
                LDSM4(Bh0, Bh1, Bh2, Bh3, b_base + aoff + np * (16 * 80) + kc * 32);
                LDSM4(Bl0, Bl1, Bl2, Bl3, b_base + aoff + (OWL - OWH) + np * (16 * 80) + kc * 32);
                MMA16816(C[np * 2 + 0], Ah0, Ah1, Ah2, Ah3, Bh0, Bh1);
                MMA16816(C[np * 2 + 0], Ah0, Ah1, Ah2, Ah3, Bl0, Bl1);
                MMA16816(C[np * 2 + 1], Ah0, Ah1, Ah2, Ah3, Bh2, Bh3);
                MMA16816(C[np * 2 + 1], Ah0, Ah1, Ah2, Ah3, Bl2, Bl3);
            }
        }
    }

    l += __shfl_xor_sync(~0u, l, 1);
    float* l_s = (float*)(dyn + OLS);
    if (q == 0) l_s[ti] = l;
    __syncthreads();

    // ---- epilogue: normalize, ELU, store from fragments ----
    {
        int r0 = 16 * w + (lane >> 2);
        int r1 = r0 + 8;
        float inv0 = 1.0f / l_s[r0];
        float inv1 = 1.0f / l_s[r1];
        float* orow0 = out + ((size_t)(b * N_ + ibase + r0)) * H_;
        float* orow1 = out + ((size_t)(b * N_ + ibase + r1)) * H_;
        int hoff = (lane & 3) * 2;
#pragma unroll
        for (int nt = 0; nt < 16; nt++) {
            int h = nt * 8 + hoff;
            float x;
            float2 o;
            x = C[nt][0] * inv0; o.x = x > 0.f ? x : expm1f(x);
            x = C[nt][1] * inv0; o.y = x > 0.f ? x : expm1f(x);
            *(float2*)(orow0 + h) = o;
            x = C[nt][2] * inv1; o.x = x > 0.f ? x : expm1f(x);
            x = C[nt][3] * inv1; o.y = x > 0.f ? x : expm1f(x);
            *(float2*)(orow1 + h) = o;
        }
    }
}

// ---------------------------------------------------------------------------
extern "C" void kernel_launch(void* const* d_in, const int* in_sizes, int n_in,
                              void* d_out, int out_size) {
    const float* inputs = (const float*)d_in[0];
    const int*   adj    = (const int*)d_in[1];
    const float* W      = (const float*)d_in[2];
    const float* bW     = (const float*)d_in[3];
    const float* a      = (const float*)d_in[4];
    const float* b_a    = (const float*)d_in[5];
    float* out = (float*)d_out;

    cudaFuncSetAttribute(k_attn_mma, cudaFuncAttributeMaxDynamicSharedMemorySize, DYNB);

    k_proj<<<(B_ * N_) / 128, 256>>>(inputs, W, bW, a, b_a);
    k_dstmax<<<B_, 256>>>();
    k_attn_mma<<<dim3(N_ / 128, B_), 256, DYNB>>>(adj, out);
}